// round 2
// baseline (speedup 1.0000x reference)
#include <cuda_runtime.h>
#include <cuda_bf16.h>
#include <cstdint>

#define NUM_USERS 100000
#define NUM_ITEMS 200000
#define N_NODES   300000
#define NNZ       1200000
#define DIM       64
#define N_LAYERS  3

// Scratch (allocation-free rule: __device__ globals)
__device__ float g_emb[N_NODES * DIM];   // current (UN-normalized) carried embeddings
__device__ float g_side[N_NODES * DIM];  // SpMM accumulator

// ---------------------------------------------------------------------------
// helpers
// ---------------------------------------------------------------------------
__device__ __forceinline__ unsigned long long dup2(float x) {
    unsigned long long r;
    asm("mov.b64 %0, {%1, %1};" : "=l"(r) : "r"(__float_as_uint(x)));
    return r;
}
__device__ __forceinline__ void ffma2(unsigned long long& acc,
                                      unsigned long long a, unsigned long long b) {
    asm("fma.rn.f32x2 %0, %1, %2, %0;" : "+l"(acc) : "l"(a), "l"(b));
}

// ---------------------------------------------------------------------------
// init: g_emb = concat(user_emb, item_emb); out[:, 0:64] = g_emb
// ---------------------------------------------------------------------------
__global__ __launch_bounds__(256) void k_init(const float* __restrict__ ue,
                                              const float* __restrict__ ie,
                                              float* __restrict__ out) {
    int idx = blockIdx.x * 256 + threadIdx.x;      // [0, N_NODES*16)
    if (idx >= N_NODES * 16) return;
    int node = idx >> 4, q = idx & 15;
    float4 v;
    if (node < NUM_USERS)
        v = ((const float4*)ue)[node * 16 + q];
    else
        v = ((const float4*)ie)[(node - NUM_USERS) * 16 + q];
    ((float4*)g_emb)[idx] = v;
    ((float4*)out)[node * 64 + q] = v;             // out row stride = 256 f32 = 64 float4
}

// ---------------------------------------------------------------------------
// zero side
// ---------------------------------------------------------------------------
__global__ __launch_bounds__(256) void k_zero() {
    int idx = blockIdx.x * 256 + threadIdx.x;
    if (idx >= N_NODES * 16) return;
    ((float4*)g_side)[idx] = make_float4(0.f, 0.f, 0.f, 0.f);
}

// ---------------------------------------------------------------------------
// SpMM: side[row] += val * emb[col]   (16 threads per edge, red.v4 atomics)
// ---------------------------------------------------------------------------
__global__ __launch_bounds__(256) void k_spmm(const int* __restrict__ rows,
                                              const int* __restrict__ cols,
                                              const float* __restrict__ vals) {
    int t = blockIdx.x * 256 + threadIdx.x;        // [0, NNZ*16)
    if (t >= NNZ * 16) return;
    int e = t >> 4, q = t & 15;
    int r = rows[e];
    int c = cols[e];
    float v = vals[e];
    float4 x = ((const float4*)g_emb)[c * 16 + q];
    float* dst = g_side + (size_t)r * 64 + q * 4;
    asm volatile("red.global.add.v4.f32 [%0], {%1,%2,%3,%4};"
                 :: "l"(dst), "f"(x.x * v), "f"(x.y * v), "f"(x.z * v), "f"(x.w * v)
                 : "memory");
}

// ---------------------------------------------------------------------------
// Fused per-layer transform:
//   A = [side | side*emb]  (K=128), B = [Wc ; We]  (128x64)
//   act = leaky_relu(A@B + bc + be, 0.2)
//   g_emb <- act (un-normalized, carried to next layer)
//   out[:, (l+1)*64:...] <- act / ||act||_2  (row L2 norm)
// Block: 64 nodes x 64 outputs, 256 threads (16x16), 4x4 per thread, f32x2 FMA.
// ---------------------------------------------------------------------------
__global__ __launch_bounds__(256) void k_gemm(const float* __restrict__ Wc,
                                              const float* __restrict__ bc,
                                              const float* __restrict__ We,
                                              const float* __restrict__ be,
                                              float* __restrict__ out, int layer) {
    extern __shared__ float sm[];
    float* sA = sm;            // [128][64]  A^T: k-major
    float* sB = sm + 128 * 64; // [128][64]
    const int tid = threadIdx.x;
    const int base = blockIdx.x * 64;

    // --- load weights (stacked [Wc ; We]) ---
    {
        const float4* wc4 = (const float4*)(Wc + layer * 4096);
        const float4* we4 = (const float4*)(We + layer * 4096);
        float4* sB4 = (float4*)sB;
        #pragma unroll
        for (int i = tid; i < 1024; i += 256) {
            sB4[i]        = wc4[i];
            sB4[1024 + i] = we4[i];
        }
    }
    // --- load A tile transposed: sA[k][node] ---
    {
        const float4* side4 = (const float4*)g_side;
        const float4* emb4  = (const float4*)g_emb;
        #pragma unroll
        for (int i = tid; i < 1024; i += 256) {
            int node = i & 63, q = i >> 6;        // q in [0,16)
            int gn = base + node;
            float4 s = make_float4(0.f, 0.f, 0.f, 0.f);
            float4 e = make_float4(0.f, 0.f, 0.f, 0.f);
            if (gn < N_NODES) { s = side4[gn * 16 + q]; e = emb4[gn * 16 + q]; }
            int k0 = q * 4;
            sA[(k0 + 0) * 64 + node] = s.x;
            sA[(k0 + 1) * 64 + node] = s.y;
            sA[(k0 + 2) * 64 + node] = s.z;
            sA[(k0 + 3) * 64 + node] = s.w;
            sA[(64 + k0 + 0) * 64 + node] = s.x * e.x;
            sA[(64 + k0 + 1) * 64 + node] = s.y * e.y;
            sA[(64 + k0 + 2) * 64 + node] = s.z * e.z;
            sA[(64 + k0 + 3) * 64 + node] = s.w * e.w;
        }
    }
    __syncthreads();

    const int tx = tid & 15;   // output cols tx*4 .. tx*4+3
    const int ty = tid >> 4;   // rows      ty*4 .. ty*4+3

    unsigned long long acc[4][2];
    #pragma unroll
    for (int r = 0; r < 4; r++) { acc[r][0] = 0ull; acc[r][1] = 0ull; }

    #pragma unroll 8
    for (int k = 0; k < 128; ++k) {
        float4 a = *(const float4*)(sA + k * 64 + ty * 4);
        const unsigned long long* bp = (const unsigned long long*)(sB + k * 64 + tx * 4);
        unsigned long long b0 = bp[0], b1 = bp[1];
        unsigned long long ax = dup2(a.x), ay = dup2(a.y),
                           az = dup2(a.z), aw = dup2(a.w);
        ffma2(acc[0][0], ax, b0); ffma2(acc[0][1], ax, b1);
        ffma2(acc[1][0], ay, b0); ffma2(acc[1][1], ay, b1);
        ffma2(acc[2][0], az, b0); ffma2(acc[2][1], az, b1);
        ffma2(acc[3][0], aw, b0); ffma2(acc[3][1], aw, b1);
    }

    // --- epilogue: bias + leaky relu + row L2 norm + stores ---
    float bias[4];
    {
        const float* bcl = bc + layer * 64 + tx * 4;
        const float* bel = be + layer * 64 + tx * 4;
        #pragma unroll
        for (int c = 0; c < 4; c++) bias[c] = __ldg(bcl + c) + __ldg(bel + c);
    }

    float4 res[4];
    float  ssq[4];
    #pragma unroll
    for (int r = 0; r < 4; r++) {
        float2 v0 = *(float2*)&acc[r][0];
        float2 v1 = *(float2*)&acc[r][1];
        float x = v0.x + bias[0];
        float y = v0.y + bias[1];
        float z = v1.x + bias[2];
        float w = v1.y + bias[3];
        x = (x > 0.f) ? x : 0.2f * x;
        y = (y > 0.f) ? y : 0.2f * y;
        z = (z > 0.f) ? z : 0.2f * z;
        w = (w > 0.f) ? w : 0.2f * w;
        res[r] = make_float4(x, y, z, w);
        ssq[r] = x * x + y * y + z * z + w * w;
    }
    // butterfly reduce across the 16 tx lanes (stays inside each half-warp group)
    #pragma unroll
    for (int off = 8; off > 0; off >>= 1) {
        ssq[0] += __shfl_xor_sync(0xffffffffu, ssq[0], off);
        ssq[1] += __shfl_xor_sync(0xffffffffu, ssq[1], off);
        ssq[2] += __shfl_xor_sync(0xffffffffu, ssq[2], off);
        ssq[3] += __shfl_xor_sync(0xffffffffu, ssq[3], off);
    }

    float4* embw = (float4*)g_emb;
    float4* out4 = (float4*)out;
    #pragma unroll
    for (int r = 0; r < 4; r++) {
        int node = base + ty * 4 + r;
        if (node < N_NODES) {
            // carry UN-normalized activation to next layer
            embw[node * 16 + tx] = res[r];
            // normalized copy goes to the output slab only
            float sc = (ssq[r] > 0.f) ? rsqrtf(ssq[r]) : 0.f;
            float4 w = make_float4(res[r].x * sc, res[r].y * sc,
                                   res[r].z * sc, res[r].w * sc);
            out4[node * 64 + (layer + 1) * 16 + tx] = w;
        }
    }
}

// ---------------------------------------------------------------------------
// launch
// ---------------------------------------------------------------------------
extern "C" void kernel_launch(void* const* d_in, const int* in_sizes, int n_in,
                              void* d_out, int out_size) {
    const int*   rows = (const int*)d_in[0];
    const int*   cols = (const int*)d_in[1];
    const float* vals = (const float*)d_in[2];
    const float* ue   = (const float*)d_in[3];
    const float* ie   = (const float*)d_in[4];
    const float* Wc   = (const float*)d_in[5];
    const float* bc   = (const float*)d_in[6];
    const float* We   = (const float*)d_in[7];
    const float* be   = (const float*)d_in[8];
    float* out = (float*)d_out;

    cudaFuncSetAttribute(k_gemm, cudaFuncAttributeMaxDynamicSharedMemorySize, 65536);

    const int n_elem4 = N_NODES * 16;                 // 4.8M float4
    k_init<<<(n_elem4 + 255) / 256, 256>>>(ue, ie, out);

    const int spmm_threads = NNZ * 16;                // 19.2M
    const int gemm_blocks  = (N_NODES + 63) / 64;     // 4688

    for (int l = 0; l < N_LAYERS; ++l) {
        k_zero<<<(n_elem4 + 255) / 256, 256>>>();
        k_spmm<<<(spmm_threads + 255) / 256, 256>>>(rows, cols, vals);
        k_gemm<<<gemm_blocks, 256, 65536>>>(Wc, bc, We, be, out, l);
    }
}